// round 16
// baseline (speedup 1.0000x reference)
#include <cuda_runtime.h>
#include <cuda_bf16.h>
#include <cuda_fp16.h>
#include <cstdint>
#include <math.h>

#define RET_ELEMS (256LL * 2048LL * 128LL)
#define DIFF_ELEMS (255LL * 2048LL * 128LL)

// Pre-transposed scratch: Wb fp16 [n][k]; W1/W2 bf16 [n][k].
__device__ __half        g_Wbh[128 * 256];
__device__ __nv_bfloat16 g_W1h[256 * 128];
__device__ __nv_bfloat16 g_W2h[128 * 256];

// ---------------------------------------------------------------------------
// helpers
// ---------------------------------------------------------------------------
__device__ __forceinline__ float gelu_exact(float x) {
    return 0.5f * x * (1.0f + erff(x * 0.7071067811865476f));
}
__device__ __forceinline__ uint32_t bfpack2(float a, float b) {
    return (uint32_t)__bfloat16_as_ushort(__float2bfloat16(a)) |
           ((uint32_t)__bfloat16_as_ushort(__float2bfloat16(b)) << 16);
}
__device__ __forceinline__ uint32_t hpack2(float a, float b) {
    return (uint32_t)__half_as_ushort(__float2half_rn(a)) |
           ((uint32_t)__half_as_ushort(__float2half_rn(b)) << 16);
}
__device__ __forceinline__ uint32_t smem_u32(const void* p) {
    uint32_t a;
    asm("{ .reg .u64 t; cvta.to.shared.u64 t, %1; cvt.u32.u64 %0, t; }" : "=r"(a) : "l"(p));
    return a;
}

__device__ __forceinline__ void mma16bf(float* d, const unsigned* a, const unsigned* b) {
    asm volatile(
        "mma.sync.aligned.m16n8k16.row.col.f32.bf16.bf16.f32 "
        "{%0,%1,%2,%3}, {%4,%5,%6,%7}, {%8,%9}, {%0,%1,%2,%3};"
        : "+f"(d[0]), "+f"(d[1]), "+f"(d[2]), "+f"(d[3])
        : "r"(a[0]), "r"(a[1]), "r"(a[2]), "r"(a[3]), "r"(b[0]), "r"(b[1]));
}
__device__ __forceinline__ void mma16h(float* d, const unsigned* a, const unsigned* b) {
    asm volatile(
        "mma.sync.aligned.m16n8k16.row.col.f32.f16.f16.f32 "
        "{%0,%1,%2,%3}, {%4,%5,%6,%7}, {%8,%9}, {%0,%1,%2,%3};"
        : "+f"(d[0]), "+f"(d[1]), "+f"(d[2]), "+f"(d[3])
        : "r"(a[0]), "r"(a[1]), "r"(a[2]), "r"(a[3]), "r"(b[0]), "r"(b[1]));
}

#define LDSM4(R, addr) \
    asm volatile("ldmatrix.sync.aligned.m8n8.x4.shared.b16 {%0,%1,%2,%3}, [%4];" \
                 : "=r"((R)[0]), "=r"((R)[1]), "=r"((R)[2]), "=r"((R)[3]) : "r"(addr))

__device__ __forceinline__ void cp16(uint32_t dst, const void* src) {
    asm volatile("cp.async.cg.shared.global [%0], [%1], 16;" :: "r"(dst), "l"(src));
}
#define CP_COMMIT asm volatile("cp.async.commit_group;" ::: "memory")
#define CP_WAIT0  asm volatile("cp.async.wait_group 0;"  ::: "memory")

// ---------------------------------------------------------------------------
// prep: transpose weights into scratch (Wb: fp16; W1/W2: bf16)
// ---------------------------------------------------------------------------
__global__ void prep_weights(const float* __restrict__ Wb,
                             const float* __restrict__ W1,
                             const float* __restrict__ W2)
{
    int i = blockIdx.x * 256 + threadIdx.x;
    if (i < 4096) {                               // g_Wbh: [128n][256k] fp16
        int n = i >> 5, k8 = i & 31;
        float v[8];
#pragma unroll
        for (int j = 0; j < 8; j++) v[j] = Wb[(k8 * 8 + j) * 128 + n];
        uint4 o = { hpack2(v[0], v[1]), hpack2(v[2], v[3]),
                    hpack2(v[4], v[5]), hpack2(v[6], v[7]) };
        *reinterpret_cast<uint4*>(&g_Wbh[n * 256 + k8 * 8]) = o;
    } else if (i < 8192) {                        // g_W1h: [256n][128k] bf16
        int idx = i - 4096;
        int n = idx >> 4, k8 = idx & 15;
        float v[8];
#pragma unroll
        for (int j = 0; j < 8; j++) v[j] = W1[(k8 * 8 + j) * 256 + n];
        uint4 o = { bfpack2(v[0], v[1]), bfpack2(v[2], v[3]),
                    bfpack2(v[4], v[5]), bfpack2(v[6], v[7]) };
        *reinterpret_cast<uint4*>(&g_W1h[n * 128 + k8 * 8]) = o;
    } else if (i < 12288) {                       // g_W2h: [128n][256k] bf16
        int idx = i - 8192;
        int n = idx >> 5, k8 = idx & 31;
        float v[8];
#pragma unroll
        for (int j = 0; j < 8; j++) v[j] = W2[(k8 * 8 + j) * 128 + n];
        uint4 o = { bfpack2(v[0], v[1]), bfpack2(v[2], v[3]),
                    bfpack2(v[4], v[5]), bfpack2(v[6], v[7]) };
        *reinterpret_cast<uint4*>(&g_W2h[n * 256 + k8 * 8]) = o;
    }
}

// ---------------------------------------------------------------------------
// Kernel A (bf16, 2 CTA/SM): ret = LayerNorm(gelu(gelu(X@W1+b1)@W2+b2) + X)
// 256 thr = 8 warps (4M x 2N), CTA 128 tokens, H in 8 chunks of 32 cols.
// W1 chunk single-buffered, W2 chunk double-buffered via cp.async.
// ---------------------------------------------------------------------------
#define FB_X    0                      // 128*272 = 34816
#define FB_W1   34816                  // 32*272  = 8704
#define FB_W2A  43520                  // 128*144 = 18432
#define FB_W2B  61952                  // 18432
#define FB_H    80384                  // 128*144 = 18432 (32 cols used)
#define FB_B1   98816                  // 1024
#define FB_B2   99840                  // 512
#define FB_G    100352                 // 512
#define FB_BE   100864                 // 512
#define FB_PS   101376                 // float2[128][2] = 2048
#define FB_SZ   103424

__global__ __launch_bounds__(256, 2)
void fused_main_kernel(const float* __restrict__ src,
                       const float* __restrict__ b1, const float* __restrict__ b2,
                       const float* __restrict__ gamma, const float* __restrict__ beta,
                       float* __restrict__ out_ret)
{
    extern __shared__ char smem[];
    const uint32_t sb = smem_u32(smem);
    float* b1s = (float*)(smem + FB_B1);
    float* b2s = (float*)(smem + FB_B2);
    float* gs  = (float*)(smem + FB_G);
    float* bs  = (float*)(smem + FB_BE);
    float2* Ps = (float2*)(smem + FB_PS);

    const int tid = threadIdx.x, lane = tid & 31, wid = tid >> 5;
    const int group = lane >> 2, tq = lane & 3;
    const int wm = wid & 3, wn = wid >> 2;       // 4M x 2N
    const int r0 = wm * 32 + group;

    const int s  = blockIdx.y;
    const int b0 = blockIdx.x * 128;
    const float* Xg = src + ((size_t)s * 2048 + b0) * 128;

    // ---- kick off chunk-0 weight staging ----
    for (int u = tid; u < 512; u += 256) {        // W1 chunk0: 32 rows x 16
        int n = u >> 4, k8 = u & 15;
        cp16(sb + FB_W1 + (uint32_t)n * 272 + k8 * 16, &g_W1h[n * 128 + k8 * 8]);
    }
    for (int u = tid; u < 512; u += 256) {        // W2 chunk0: 128 rows x 4
        int n = u >> 2, k8 = u & 3;
        cp16(sb + FB_W2A + (uint32_t)n * 144 + k8 * 16, &g_W2h[n * 256 + k8 * 8]);
    }
    CP_COMMIT;

    // ---- stage X as bf16 (stride 272) ----
    for (int u = tid; u < 2048; u += 256) {
        int row = u >> 4, c8 = u & 15;
        const float4* p = reinterpret_cast<const float4*>(Xg + row * 128 + c8 * 8);
        float4 lo = p[0], hi = p[1];
        uint4 o = { bfpack2(lo.x, lo.y), bfpack2(lo.z, lo.w),
                    bfpack2(hi.x, hi.y), bfpack2(hi.z, hi.w) };
        *reinterpret_cast<uint4*>(smem + FB_X + row * 272 + c8 * 16) = o;
    }
    b1s[tid] = b1[tid];
    if (tid < 128) { b2s[tid] = b2[tid]; gs[tid] = gamma[tid]; bs[tid] = beta[tid]; }
    CP_WAIT0;
    __syncthreads();

    // LDSM addressing
    const int lm = lane & 15, lh = lane >> 4;
    const int bn = (lane & 7) + ((lane >> 4) << 3);
    const int bkB = ((lane >> 3) & 1) * 16;
    const uint32_t aX  = sb + FB_X + (uint32_t)(wm * 32 + lm) * 272 + lh * 16;
    const uint32_t aX1 = aX + 16 * 272;
    const uint32_t bW1b = sb + FB_W1 + (uint32_t)(wn * 16 + bn) * 272 + bkB;
    const uint32_t aH  = sb + FB_H + (uint32_t)(wm * 32 + lm) * 144 + lh * 16;
    const uint32_t aH1 = aH + 16 * 144;
    const uint32_t b2off = (uint32_t)(wn * 64 + bn) * 144 + bkB;   // + q*16*144

    float acc2[16][4];
#pragma unroll
    for (int i = 0; i < 16; i++) { acc2[i][0] = acc2[i][1] = acc2[i][2] = acc2[i][3] = 0.f; }

#pragma unroll 1
    for (int c = 0; c < 8; ++c) {
        // ---- GEMM1: Hc = X @ W1c (warp 32x16, K=128 -> 8 k16-steps) ----
        float acc1[4][4];
#pragma unroll
        for (int i = 0; i < 4; i++) { acc1[i][0] = acc1[i][1] = acc1[i][2] = acc1[i][3] = 0.f; }
#pragma unroll
        for (int ks = 0; ks < 8; ks++) {
            unsigned A0[4], A1[4], B[4];
            LDSM4(A0, aX  + ks * 32);
            LDSM4(A1, aX1 + ks * 32);
            LDSM4(B,  bW1b + ks * 32);
            mma16bf(acc1[0], A0, B);  mma16bf(acc1[1], A0, B + 2);
            mma16bf(acc1[2], A1, B);  mma16bf(acc1[3], A1, B + 2);
        }

        // ---- epilogue-1: H = bf16(gelu(acc1 + b1)) ----
#pragma unroll
        for (int mt = 0; mt < 2; mt++) {
#pragma unroll
            for (int nt = 0; nt < 2; nt++) {
                int col = wn * 16 + nt * 8 + 2 * tq;          // 0..31 within chunk
                int rA = r0 + mt * 16, rB = rA + 8;
                float bi0 = b1s[c * 32 + col], bi1 = b1s[c * 32 + col + 1];
                float* v = acc1[mt * 2 + nt];
                *reinterpret_cast<uint32_t*>(smem + FB_H + rA * 144 + col * 2) =
                    bfpack2(gelu_exact(v[0] + bi0), gelu_exact(v[1] + bi1));
                *reinterpret_cast<uint32_t*>(smem + FB_H + rB * 144 + col * 2) =
                    bfpack2(gelu_exact(v[2] + bi0), gelu_exact(v[3] + bi1));
            }
        }
        __syncthreads();   // Hc visible; GEMM1 reads of W1C done

        // ---- overlap: stage chunk c+1 weights while GEMM2 runs ----
        if (c < 7) {
            int cn = c + 1;
            uint32_t w2n = sb + ((cn & 1) ? FB_W2B : FB_W2A);
            for (int u = tid; u < 512; u += 256) {
                int n = u >> 4, k8 = u & 15;
                cp16(sb + FB_W1 + (uint32_t)n * 272 + k8 * 16,
                     &g_W1h[(cn * 32 + n) * 128 + k8 * 8]);
            }
            for (int u = tid; u < 512; u += 256) {
                int n = u >> 2, k8 = u & 3;
                cp16(w2n + (uint32_t)n * 144 + k8 * 16,
                     &g_W2h[n * 256 + cn * 32 + k8 * 8]);
            }
            CP_COMMIT;
        }

        // ---- GEMM2: acc2 += Hc @ W2c (warp 32x64, K=32 -> 2 k16-steps) ----
        {
            const uint32_t w2b = sb + ((c & 1) ? FB_W2B : FB_W2A) + b2off - sb;
            const uint32_t base = sb + ((c & 1) ? FB_W2B : FB_W2A);
            (void)w2b;
#pragma unroll
            for (int ks = 0; ks < 2; ks++) {
                unsigned A0[4], A1[4], B[4][4];
                LDSM4(A0, aH  + ks * 32);
                LDSM4(A1, aH1 + ks * 32);
#pragma unroll
                for (int q = 0; q < 4; q++)
                    LDSM4(B[q], base + b2off + q * (16 * 144) + ks * 32);
#pragma unroll
                for (int q = 0; q < 4; q++) {
                    mma16bf(acc2[q * 2],     A0, B[q]);
                    mma16bf(acc2[q * 2 + 1], A0, B[q] + 2);
                    mma16bf(acc2[8 + q * 2],     A1, B[q]);
                    mma16bf(acc2[8 + q * 2 + 1], A1, B[q] + 2);
                }
            }
        }
        CP_WAIT0;
        __syncthreads();   // GEMM2 done (H reusable), next weights landed
    }

    // ---- epilogue-2: r = gelu(acc2+b2)+X (fp32 from gmem); LayerNorm ----
    float sums[4] = {0, 0, 0, 0}, sqs[4] = {0, 0, 0, 0};
    const float2* Xg2 = (const float2*)Xg;
#pragma unroll
    for (int mt = 0; mt < 2; mt++) {
#pragma unroll
        for (int nt = 0; nt < 8; nt++) {
            int col = wn * 64 + nt * 8 + 2 * tq;
            int rA = r0 + mt * 16, rB = rA + 8;
            float2 xa = Xg2[rA * 64 + (col >> 1)];
            float2 xb = Xg2[rB * 64 + (col >> 1)];
            float* v = acc2[mt * 8 + nt];
            v[0] = gelu_exact(v[0] + b2s[col])     + xa.x;
            v[1] = gelu_exact(v[1] + b2s[col + 1]) + xa.y;
            v[2] = gelu_exact(v[2] + b2s[col])     + xb.x;
            v[3] = gelu_exact(v[3] + b2s[col + 1]) + xb.y;
            sums[mt * 2]     += v[0] + v[1]; sqs[mt * 2]     += v[0] * v[0] + v[1] * v[1];
            sums[mt * 2 + 1] += v[2] + v[3]; sqs[mt * 2 + 1] += v[2] * v[2] + v[3] * v[3];
        }
    }
#pragma unroll
    for (int j = 0; j < 4; j++) {
#pragma unroll
        for (int o = 1; o < 4; o <<= 1) {
            sums[j] += __shfl_xor_sync(0xffffffffu, sums[j], o);
            sqs[j]  += __shfl_xor_sync(0xffffffffu, sqs[j],  o);
        }
    }
    if (tq == 0) {
#pragma unroll
        for (int j = 0; j < 4; j++) Ps[(r0 + j * 8) * 2 + wn] = make_float2(sums[j], sqs[j]);
    }
    __syncthreads();
    float mus[4], rss[4];
#pragma unroll
    for (int j = 0; j < 4; j++) {
        int row = r0 + j * 8;
        float2 p0 = Ps[row * 2], p1 = Ps[row * 2 + 1];
        float mu  = (p0.x + p1.x) * (1.f / 128.f);
        float var = (p0.y + p1.y) * (1.f / 128.f) - mu * mu;
        mus[j] = mu; rss[j] = rsqrtf(var + 1e-5f);
    }
    float2* og2 = (float2*)(out_ret + ((size_t)s * 2048 + b0) * 128);
#pragma unroll
    for (int mt = 0; mt < 2; mt++) {
#pragma unroll
        for (int nt = 0; nt < 8; nt++) {
            int col = wn * 64 + nt * 8 + 2 * tq;
            int rA = r0 + mt * 16, rB = rA + 8;
            float* v = acc2[mt * 8 + nt];
            float muA = mus[mt * 2],     rsA = rss[mt * 2];
            float muB = mus[mt * 2 + 1], rsB = rss[mt * 2 + 1];
            og2[rA * 64 + (col >> 1)] =
                make_float2((v[0] - muA) * rsA * gs[col]     + bs[col],
                            (v[1] - muA) * rsA * gs[col + 1] + bs[col + 1]);
            og2[rB * 64 + (col >> 1)] =
                make_float2((v[2] - muB) * rsB * gs[col]     + bs[col],
                            (v[3] - muB) * rsB * gs[col + 1] + bs[col + 1]);
        }
    }
}

// ---------------------------------------------------------------------------
// Kernel B (persistent, fp16, 2 CTA/SM): diffs[s-1] = gelu([X_{s-1}|X_s]@Wb+bb)
// 256 thr = 8 warps (2M x 4N), CTA b-tile 64 tokens, 15 steps per CTA.
// Compile-time buffer roles (R15-proven control flow).
// ---------------------------------------------------------------------------
#define PH_WB   0                      // 128*528 = 67584
#define PH_X0   67584                  // 64*272  = 17408
#define PH_X1   84992                  // 17408
#define PH_BB   102400                 // 512
#define PH_SZ   102912
#define PH_SGRP 17                     // 17 * 15 = 255 steps exactly
#define PH_SPG  15

__global__ __launch_bounds__(256, 2)
void bracket_kernel(const float* __restrict__ src,
                    const float* __restrict__ bb,
                    float* __restrict__ out_diffs, float* __restrict__ cond)
{
    extern __shared__ char smem[];
    const uint32_t sb = smem_u32(smem);
    float* bbs = (float*)(smem + PH_BB);
    char* X0g = smem + PH_X0;
    char* X1g = smem + PH_X1;

    const int tid = threadIdx.x, lane = tid & 31, wid = tid >> 5;
    const int group = lane >> 2, tq = lane & 3;
    const int wm = wid & 1, wn = wid >> 1;       // 2M x 4N
    const int r0 = wm * 32 + group;

    const int b0 = blockIdx.x * 64;
    const int sg = blockIdx.y;
    const int s0 = 1 + sg * PH_SPG;
    const int sEnd = s0 + PH_SPG;
    if (blockIdx.x == 0 && sg == 0 && tid < 3) cond[tid] = 0.f;

    // ---- stage Wb fp16 resident ----
    for (int u = tid; u < 4096; u += 256) {
        int n = u >> 5, k8 = u & 31;
        cp16(sb + PH_WB + (uint32_t)n * 528 + k8 * 16, &g_Wbh[n * 256 + k8 * 8]);
    }
    CP_COMMIT;
    if (tid < 128) bbs[tid] = bb[tid];

    // ---- stage X_{s0-1} -> X0, X_{s0} -> X1 (fp16, stride 272) ----
#pragma unroll
    for (int i = 0; i < 4; i++) {
        int idx = tid + i * 256;                  // 0..1023
        int row = idx >> 4, c8 = idx & 15;
        const float4* pp = reinterpret_cast<const float4*>(
            src + ((size_t)(s0 - 1) * 2048 + b0 + row) * 128 + c8 * 8);
        const float4* pc = reinterpret_cast<const float4*>(
            src + ((size_t)s0 * 2048 + b0 + row) * 128 + c8 * 8);
        float4 pl = pp[0], ph = pp[1], cl = pc[0], ch = pc[1];
        *reinterpret_cast<uint4*>(X0g + row * 272 + c8 * 16) =
            make_uint4(hpack2(pl.x, pl.y), hpack2(pl.z, pl.w),
                       hpack2(ph.x, ph.y), hpack2(ph.z, ph.w));
        *reinterpret_cast<uint4*>(X1g + row * 272 + c8 * 16) =
            make_uint4(hpack2(cl.x, cl.y), hpack2(cl.z, cl.w),
                       hpack2(ch.x, ch.y), hpack2(ch.z, ch.w));
    }
    CP_WAIT0;
    __syncthreads();

    // LDSM addressing
    const int lm = lane & 15, lh = lane >> 4;
    const int bn = (lane & 7) + ((lane >> 4) << 3);
    const int bkB = ((lane >> 3) & 1) * 16;
    const uint32_t aoff0 = (uint32_t)(wm * 32 + lm) * 272 + lh * 16;
    const uint32_t aoff1 = aoff0 + 16 * 272;
    const uint32_t bW0 = sb + PH_WB + (uint32_t)(wn * 32 + bn) * 528 + bkB;
    const uint32_t bW1 = bW0 + 16 * 528;

    auto do_step = [&](int s, uint32_t P, uint32_t C, char* Pg) {
        float acc[8][4];
#pragma unroll
        for (int i = 0; i < 8; i++) { acc[i][0] = acc[i][1] = acc[i][2] = acc[i][3] = 0.f; }

        // ksteps 0..7: A = X_{s-1} (P), B = Wb k 0..127
#pragma unroll
        for (int ks = 0; ks < 8; ks++) {
            unsigned A0[4], A1[4], B0f[4], B1f[4];
            LDSM4(A0,  P + aoff0 + ks * 32);
            LDSM4(A1,  P + aoff1 + ks * 32);
            LDSM4(B0f, bW0 + ks * 32);
            LDSM4(B1f, bW1 + ks * 32);
            mma16h(acc[0], A0, B0f);  mma16h(acc[1], A0, B0f + 2);
            mma16h(acc[2], A0, B1f);  mma16h(acc[3], A0, B1f + 2);
            mma16h(acc[4], A1, B0f);  mma16h(acc[5], A1, B0f + 2);
            mma16h(acc[6], A1, B1f);  mma16h(acc[7], A1, B1f + 2);
        }
        __syncthreads();   // all warps done reading P

        const bool pf = (s + 1 < sEnd);
        float4 xr[8];
        if (pf) {
#pragma unroll
            for (int i = 0; i < 4; i++) {
                int idx = tid + i * 256;
                int row = idx >> 4, c8 = idx & 15;
                const float4* p = reinterpret_cast<const float4*>(
                    src + ((size_t)(s + 1) * 2048 + b0 + row) * 128 + c8 * 8);
                xr[i * 2]     = p[0];
                xr[i * 2 + 1] = p[1];
            }
        }

        // ksteps 8..15: A = X_s (C), B = Wb k 128..255
#pragma unroll
        for (int ks = 8; ks < 16; ks++) {
            unsigned A0[4], A1[4], B0f[4], B1f[4];
            LDSM4(A0,  C + aoff0 + (ks - 8) * 32);
            LDSM4(A1,  C + aoff1 + (ks - 8) * 32);
            LDSM4(B0f, bW0 + ks * 32);
            LDSM4(B1f, bW1 + ks * 32);
            mma16h(acc[0], A0, B0f);  mma16h(acc[1], A0, B0f + 2);
            mma16h(acc[2], A0, B1f);  mma16h(acc[3], A0, B1f + 2);
            mma16h(acc[4], A1, B0f);  mma16h(acc[5], A1, B0f + 2);
            mma16h(acc[6], A1, B1f);  mma16h(acc[7], A1, B1f + 2);
        }

        // refill P with X_{s+1}
        if (pf) {
#pragma unroll
            for (int i = 0; i < 4; i++) {
                int idx = tid + i * 256;
                int row = idx >> 4, c8 = idx & 15;
                float4 lo = xr[i * 2], hi = xr[i * 2 + 1];
                *reinterpret_cast<uint4*>(Pg + row * 272 + c8 * 16) =
                    make_uint4(hpack2(lo.x, lo.y), hpack2(lo.z, lo.w),
                               hpack2(hi.x, hi.y), hpack2(hi.z, hi.w));
            }
        }

        // epilogue: gelu(acc + bb) -> diffs[s-1]
        {
            float2* og2 = (float2*)(out_diffs + ((size_t)(s - 1) * 2048 + b0) * 128);
#pragma unroll
            for (int mt = 0; mt < 2; mt++) {
#pragma unroll
                for (int nt = 0; nt < 2; nt++) {
                    int col = wn * 32 + nt * 8 + 2 * tq;
                    int rA = r0 + mt * 16, rB = rA + 8;
                    float bi0 = bbs[col], bi1 = bbs[col + 1];
                    float* v0 = acc[mt * 4 + nt];       // ntiles 0,1 = B0f
                    float* v1 = acc[mt * 4 + nt + 2];   // ntiles 2,3 = B1f
                    og2[rA * 64 + (col >> 1)] = make_float2(gelu_exact(v0[0] + bi0),
                                                            gelu_exact(v0[1] + bi1));
                    og2[rB * 64 + (col >> 1)] = make_float2(gelu_exact(v0[2] + bi0),
                                                            gelu_exact(v0[3] + bi1));
                    int col2 = col + 16;
                    float bj0 = bbs[col2], bj1 = bbs[col2 + 1];
                    og2[rA * 64 + (col2 >> 1)] = make_float2(gelu_exact(v1[0] + bj0),
                                                             gelu_exact(v1[1] + bj1));
                    og2[rB * 64 + (col2 >> 1)] = make_float2(gelu_exact(v1[2] + bj0),
                                                             gelu_exact(v1[3] + bj1));
                }
            }
        }
        __syncthreads();   // P refill visible before next step reads it as C
    };

    int s = s0;
    do_step(s, sb + PH_X0, sb + PH_X1, X0g); ++s;
#pragma unroll 1
    for (int it = 0; it < 7; ++it) {
        do_step(s, sb + PH_X1, sb + PH_X0, X1g); ++s;
        do_step(s, sb + PH_X0, sb + PH_X1, X0g); ++s;
    }
}

// ---------------------------------------------------------------------------
// launcher
// ---------------------------------------------------------------------------
extern "C" void kernel_launch(void* const* d_in, const int* in_sizes, int n_in,
                              void* d_out, int out_size)
{
    const float* src   = (const float*)d_in[0];
    const float* Wb    = (const float*)d_in[1];
    const float* bb    = (const float*)d_in[2];
    const float* W1    = (const float*)d_in[3];
    const float* b1    = (const float*)d_in[4];
    const float* W2    = (const float*)d_in[5];
    const float* b2    = (const float*)d_in[6];
    const float* gamma = (const float*)d_in[7];
    const float* beta  = (const float*)d_in[8];
    float* out = (float*)d_out;

    cudaFuncSetAttribute(fused_main_kernel, cudaFuncAttributeMaxDynamicSharedMemorySize, FB_SZ);
    cudaFuncSetAttribute(bracket_kernel,    cudaFuncAttributeMaxDynamicSharedMemorySize, PH_SZ);

    prep_weights<<<48, 256>>>(Wb, W1, W2);

    dim3 gA(16, 256);
    dim3 gB(32, PH_SGRP);
    fused_main_kernel<<<gA, 256, FB_SZ>>>(src, b1, b2, gamma, beta, out);
    bracket_kernel<<<gB, 256, PH_SZ>>>(src, bb,
                                       out + RET_ELEMS,
                                       out + RET_ELEMS + DIFF_ELEMS);
}

// round 17
// speedup vs baseline: 1.3097x; 1.3097x over previous
#include <cuda_runtime.h>
#include <cuda_bf16.h>
#include <cuda_fp16.h>
#include <cstdint>
#include <math.h>

#define RET_ELEMS (256LL * 2048LL * 128LL)
#define DIFF_ELEMS (255LL * 2048LL * 128LL)

// Pre-transposed scratch: Wb fp16 [n][k]; W1/W2 bf16 [n][k].
__device__ __half        g_Wbh[128 * 256];
__device__ __nv_bfloat16 g_W1h[256 * 128];
__device__ __nv_bfloat16 g_W2h[128 * 256];

// ---------------------------------------------------------------------------
// helpers
// ---------------------------------------------------------------------------
__device__ __forceinline__ float gelu_exact(float x) {
    return 0.5f * x * (1.0f + erff(x * 0.7071067811865476f));
}
__device__ __forceinline__ uint32_t bfpack2(float a, float b) {
    return (uint32_t)__bfloat16_as_ushort(__float2bfloat16(a)) |
           ((uint32_t)__bfloat16_as_ushort(__float2bfloat16(b)) << 16);
}
__device__ __forceinline__ uint32_t hpack2(float a, float b) {
    return (uint32_t)__half_as_ushort(__float2half_rn(a)) |
           ((uint32_t)__half_as_ushort(__float2half_rn(b)) << 16);
}
__device__ __forceinline__ uint32_t smem_u32(const void* p) {
    uint32_t a;
    asm("{ .reg .u64 t; cvta.to.shared.u64 t, %1; cvt.u32.u64 %0, t; }" : "=r"(a) : "l"(p));
    return a;
}

__device__ __forceinline__ void mma16bf(float* d, const unsigned* a, const unsigned* b) {
    asm volatile(
        "mma.sync.aligned.m16n8k16.row.col.f32.bf16.bf16.f32 "
        "{%0,%1,%2,%3}, {%4,%5,%6,%7}, {%8,%9}, {%0,%1,%2,%3};"
        : "+f"(d[0]), "+f"(d[1]), "+f"(d[2]), "+f"(d[3])
        : "r"(a[0]), "r"(a[1]), "r"(a[2]), "r"(a[3]), "r"(b[0]), "r"(b[1]));
}
__device__ __forceinline__ void mma16h(float* d, const unsigned* a, const unsigned* b) {
    asm volatile(
        "mma.sync.aligned.m16n8k16.row.col.f32.f16.f16.f32 "
        "{%0,%1,%2,%3}, {%4,%5,%6,%7}, {%8,%9}, {%0,%1,%2,%3};"
        : "+f"(d[0]), "+f"(d[1]), "+f"(d[2]), "+f"(d[3])
        : "r"(a[0]), "r"(a[1]), "r"(a[2]), "r"(a[3]), "r"(b[0]), "r"(b[1]));
}

#define LDSM4(R, addr) \
    asm volatile("ldmatrix.sync.aligned.m8n8.x4.shared.b16 {%0,%1,%2,%3}, [%4];" \
                 : "=r"((R)[0]), "=r"((R)[1]), "=r"((R)[2]), "=r"((R)[3]) : "r"(addr))

__device__ __forceinline__ void cp16(uint32_t dst, const void* src) {
    asm volatile("cp.async.cg.shared.global [%0], [%1], 16;" :: "r"(dst), "l"(src));
}
#define CP_COMMIT asm volatile("cp.async.commit_group;" ::: "memory")
#define CP_WAIT0  asm volatile("cp.async.wait_group 0;"  ::: "memory")

// ---------------------------------------------------------------------------
// prep: transpose weights into scratch (Wb: fp16; W1/W2: bf16)
// ---------------------------------------------------------------------------
__global__ void prep_weights(const float* __restrict__ Wb,
                             const float* __restrict__ W1,
                             const float* __restrict__ W2)
{
    int i = blockIdx.x * 256 + threadIdx.x;
    if (i < 4096) {                               // g_Wbh: [128n][256k] fp16
        int n = i >> 5, k8 = i & 31;
        float v[8];
#pragma unroll
        for (int j = 0; j < 8; j++) v[j] = Wb[(k8 * 8 + j) * 128 + n];
        uint4 o = { hpack2(v[0], v[1]), hpack2(v[2], v[3]),
                    hpack2(v[4], v[5]), hpack2(v[6], v[7]) };
        *reinterpret_cast<uint4*>(&g_Wbh[n * 256 + k8 * 8]) = o;
    } else if (i < 8192) {                        // g_W1h: [256n][128k] bf16
        int idx = i - 4096;
        int n = idx >> 4, k8 = idx & 15;
        float v[8];
#pragma unroll
        for (int j = 0; j < 8; j++) v[j] = W1[(k8 * 8 + j) * 256 + n];
        uint4 o = { bfpack2(v[0], v[1]), bfpack2(v[2], v[3]),
                    bfpack2(v[4], v[5]), bfpack2(v[6], v[7]) };
        *reinterpret_cast<uint4*>(&g_W1h[n * 128 + k8 * 8]) = o;
    } else if (i < 12288) {                       // g_W2h: [128n][256k] bf16
        int idx = i - 8192;
        int n = idx >> 5, k8 = idx & 31;
        float v[8];
#pragma unroll
        for (int j = 0; j < 8; j++) v[j] = W2[(k8 * 8 + j) * 128 + n];
        uint4 o = { bfpack2(v[0], v[1]), bfpack2(v[2], v[3]),
                    bfpack2(v[4], v[5]), bfpack2(v[6], v[7]) };
        *reinterpret_cast<uint4*>(&g_W2h[n * 256 + k8 * 8]) = o;
    }
}

// ---------------------------------------------------------------------------
// Kernel A (bf16): ret = LayerNorm(gelu(gelu(X@W1+b1)@W2+b2) + X)
// R15 base + double-buffered H: one barrier per chunk (before GEMM2).
// 512 thr = 16 warps (4M x 4N), W1/W2 resident, H in 4 chunks of 64.
// ---------------------------------------------------------------------------
#define FB_W1   0                      // 256*272 = 69632
#define FB_W2   69632                  // 128*528 = 67584
#define FB_X    137216                 // 128*272 = 34816
#define FB_H0   172032                 // 128*144 = 18432
#define FB_H1   190464                 // 18432
#define FB_B1   208896                 // 1024
#define FB_B2   209920                 // 512
#define FB_G    210432                 // 512
#define FB_BE   210944                 // 512
#define FB_PS   211456                 // 4096
#define FB_SZ   215552

__global__ __launch_bounds__(512, 1)
void fused_main_kernel(const float* __restrict__ src,
                       const float* __restrict__ b1, const float* __restrict__ b2,
                       const float* __restrict__ gamma, const float* __restrict__ beta,
                       float* __restrict__ out_ret)
{
    extern __shared__ char smem[];
    const uint32_t sb = smem_u32(smem);
    float* b1s = (float*)(smem + FB_B1);
    float* b2s = (float*)(smem + FB_B2);
    float* gs  = (float*)(smem + FB_G);
    float* bs  = (float*)(smem + FB_BE);
    float2* Ps = (float2*)(smem + FB_PS);

    const int tid = threadIdx.x, lane = tid & 31, wid = tid >> 5;
    const int group = lane >> 2, tq = lane & 3;
    const int wm = wid & 3, wn = wid >> 2;       // 4M x 4N
    const int r0 = wm * 32 + group;

    const int s  = blockIdx.y;
    const int b0 = blockIdx.x * 128;
    const float* Xg = src + ((size_t)s * 2048 + b0) * 128;

    for (int u = tid; u < 4096; u += 512) {
        int n = u >> 4, k8 = u & 15;
        cp16(sb + FB_W1 + (uint32_t)n * 272 + k8 * 16, &g_W1h[n * 128 + k8 * 8]);
    }
    for (int u = tid; u < 4096; u += 512) {
        int n = u >> 5, k8 = u & 31;
        cp16(sb + FB_W2 + (uint32_t)n * 528 + k8 * 16, &g_W2h[n * 256 + k8 * 8]);
    }
    CP_COMMIT;

    for (int u = tid; u < 2048; u += 512) {
        int row = u >> 4, c8 = u & 15;
        const float4* p = reinterpret_cast<const float4*>(Xg + row * 128 + c8 * 8);
        float4 lo = p[0], hi = p[1];
        uint4 o = { bfpack2(lo.x, lo.y), bfpack2(lo.z, lo.w),
                    bfpack2(hi.x, hi.y), bfpack2(hi.z, hi.w) };
        *reinterpret_cast<uint4*>(smem + FB_X + row * 272 + c8 * 16) = o;
    }
    if (tid < 256) b1s[tid] = b1[tid];
    if (tid < 128) { b2s[tid] = b2[tid]; gs[tid] = gamma[tid]; bs[tid] = beta[tid]; }
    CP_WAIT0;
    __syncthreads();

    const int lm = lane & 15, lh = lane >> 4;
    const int bn = (lane & 7) + ((lane >> 4) << 3);
    const int bkB = ((lane >> 3) & 1) * 16;
    const uint32_t aX  = sb + FB_X + (uint32_t)(wm * 32 + lm) * 272 + lh * 16;
    const uint32_t aX1 = aX + 16 * 272;
    const uint32_t bW1b = sb + FB_W1 + (uint32_t)(wn * 16 + bn) * 272 + bkB;
    const uint32_t aHoff = (uint32_t)(wm * 32 + lm) * 144 + lh * 16;
    const uint32_t bW2b = sb + FB_W2 + (uint32_t)(wn * 32 + bn) * 528 + bkB;
    const uint32_t bW2b1 = bW2b + 16 * 528;

    float acc2[8][4];
#pragma unroll
    for (int i = 0; i < 8; i++) { acc2[i][0] = acc2[i][1] = acc2[i][2] = acc2[i][3] = 0.f; }

#pragma unroll
    for (int c = 0; c < 4; ++c) {
        const uint32_t hOff = (c & 1) ? FB_H1 : FB_H0;

        // ---- GEMM1: Hc = X @ W1c (warp 32x16, K=128 -> 8 k16-steps) ----
        float acc1[4][4];
#pragma unroll
        for (int i = 0; i < 4; i++) { acc1[i][0] = acc1[i][1] = acc1[i][2] = acc1[i][3] = 0.f; }
        {
            const uint32_t bw = bW1b + (uint32_t)c * 17408;
#pragma unroll
            for (int ks = 0; ks < 8; ks++) {
                unsigned A0[4], A1[4], B[4];
                LDSM4(A0, aX  + ks * 32);
                LDSM4(A1, aX1 + ks * 32);
                LDSM4(B,  bw  + ks * 32);
                mma16bf(acc1[0], A0, B);  mma16bf(acc1[1], A0, B + 2);
                mma16bf(acc1[2], A1, B);  mma16bf(acc1[3], A1, B + 2);
            }
        }

        // ---- epilogue-1: H[c&1] = bf16(gelu(acc1 + b1)) ----
#pragma unroll
        for (int mt = 0; mt < 2; mt++) {
#pragma unroll
            for (int nt = 0; nt < 2; nt++) {
                int col = wn * 16 + nt * 8 + 2 * tq;
                int rA = r0 + mt * 16, rB = rA + 8;
                float bi0 = b1s[c * 64 + col], bi1 = b1s[c * 64 + col + 1];
                float* v = acc1[mt * 2 + nt];
                *reinterpret_cast<uint32_t*>(smem + hOff + rA * 144 + col * 2) =
                    bfpack2(gelu_exact(v[0] + bi0), gelu_exact(v[1] + bi1));
                *reinterpret_cast<uint32_t*>(smem + hOff + rB * 144 + col * 2) =
                    bfpack2(gelu_exact(v[2] + bi0), gelu_exact(v[3] + bi1));
            }
        }
        __syncthreads();   // Hc visible to all warps (single barrier per chunk)

        // ---- GEMM2: acc2 += Hc @ W2c (warp 32x32, K=64 -> 4 k16-steps) ----
        {
            const uint32_t aH  = sb + hOff + aHoff;
            const uint32_t aH1 = aH + 16 * 144;
            const uint32_t bw0 = bW2b  + (uint32_t)c * 128;
            const uint32_t bw1 = bW2b1 + (uint32_t)c * 128;
#pragma unroll
            for (int ks = 0; ks < 4; ks++) {
                unsigned A0[4], A1[4], B0[4], B1[4];
                LDSM4(A0, aH  + ks * 32);
                LDSM4(A1, aH1 + ks * 32);
                LDSM4(B0, bw0 + ks * 32);
                LDSM4(B1, bw1 + ks * 32);
                mma16bf(acc2[0], A0, B0);  mma16bf(acc2[1], A0, B0 + 2);
                mma16bf(acc2[2], A0, B1);  mma16bf(acc2[3], A0, B1 + 2);
                mma16bf(acc2[4], A1, B0);  mma16bf(acc2[5], A1, B0 + 2);
                mma16bf(acc2[6], A1, B1);  mma16bf(acc2[7], A1, B1 + 2);
            }
        }
        // no barrier: next chunk's GEMM1/epi1 touch X/W1/H[other parity] only
    }

    // ---- epilogue-2: r = gelu(acc2+b2)+X (fp32 from gmem) ; LayerNorm ----
    float sums[4] = {0, 0, 0, 0}, sqs[4] = {0, 0, 0, 0};
    const float2* Xg2 = (const float2*)Xg;
#pragma unroll
    for (int mt = 0; mt < 2; mt++) {
#pragma unroll
        for (int nt = 0; nt < 4; nt++) {
            int col = wn * 32 + nt * 8 + 2 * tq;
            int rA = r0 + mt * 16, rB = rA + 8;
            float2 xa = Xg2[rA * 64 + (col >> 1)];
            float2 xb = Xg2[rB * 64 + (col >> 1)];
            float* v = acc2[mt * 4 + nt];
            v[0] = gelu_exact(v[0] + b2s[col])     + xa.x;
            v[1] = gelu_exact(v[1] + b2s[col + 1]) + xa.y;
            v[2] = gelu_exact(v[2] + b2s[col])     + xb.x;
            v[3] = gelu_exact(v[3] + b2s[col + 1]) + xb.y;
            sums[mt * 2]     += v[0] + v[1]; sqs[mt * 2]     += v[0] * v[0] + v[1] * v[1];
            sums[mt * 2 + 1] += v[2] + v[3]; sqs[mt * 2 + 1] += v[2] * v[2] + v[3] * v[3];
        }
    }
#pragma unroll
    for (int j = 0; j < 4; j++) {
#pragma unroll
        for (int o = 1; o < 4; o <<= 1) {
            sums[j] += __shfl_xor_sync(0xffffffffu, sums[j], o);
            sqs[j]  += __shfl_xor_sync(0xffffffffu, sqs[j],  o);
        }
    }
    if (tq == 0) {
#pragma unroll
        for (int j = 0; j < 4; j++) Ps[(r0 + j * 8) * 4 + wn] = make_float2(sums[j], sqs[j]);
    }
    __syncthreads();
    float mus[4], rss[4];
#pragma unroll
    for (int j = 0; j < 4; j++) {
        int row = r0 + j * 8;
        float ssum = 0.f, ssq = 0.f;
#pragma unroll
        for (int w = 0; w < 4; w++) { float2 p = Ps[row * 4 + w]; ssum += p.x; ssq += p.y; }
        float mu  = ssum * (1.f / 128.f);
        float var = ssq * (1.f / 128.f) - mu * mu;
        mus[j] = mu; rss[j] = rsqrtf(var + 1e-5f);
    }
    float2* og2 = (float2*)(out_ret + ((size_t)s * 2048 + b0) * 128);
#pragma unroll
    for (int mt = 0; mt < 2; mt++) {
#pragma unroll
        for (int nt = 0; nt < 4; nt++) {
            int col = wn * 32 + nt * 8 + 2 * tq;
            int rA = r0 + mt * 16, rB = rA + 8;
            float* v = acc2[mt * 4 + nt];
            float muA = mus[mt * 2],     rsA = rss[mt * 2];
            float muB = mus[mt * 2 + 1], rsB = rss[mt * 2 + 1];
            og2[rA * 64 + (col >> 1)] =
                make_float2((v[0] - muA) * rsA * gs[col]     + bs[col],
                            (v[1] - muA) * rsA * gs[col + 1] + bs[col + 1]);
            og2[rB * 64 + (col >> 1)] =
                make_float2((v[2] - muB) * rsB * gs[col]     + bs[col],
                            (v[3] - muB) * rsB * gs[col + 1] + bs[col + 1]);
        }
    }
}

// ---------------------------------------------------------------------------
// Kernel B (persistent, fp16): diffs[s-1] = gelu([X_{s-1}|X_s] @ Wb + bb)
// R15 base + 3-buffer X rotation: ONE barrier per step.
// Roles: P = X_{s-1} (read ksteps 0-7), C = X_s (read 8-15), D = free (gets X_{s+1}).
// Rotation (X0,X1,X2)->(X1,X2,X0)->(X2,X0,X1); 15 steps = 5 x 3.
// ---------------------------------------------------------------------------
#define PH_WB   0                      // 128*528 = 67584
#define PH_X0   67584                  // 128*272 = 34816
#define PH_X1   102400                 // 34816
#define PH_X2   137216                 // 34816
#define PH_BB   172032                 // 512
#define PH_SZ   172544
#define PH_SGRP 17                     // 17 * 15 = 255 steps exactly
#define PH_SPG  15

__global__ __launch_bounds__(512, 1)
void bracket_kernel(const float* __restrict__ src,
                    const float* __restrict__ bb,
                    float* __restrict__ out_diffs, float* __restrict__ cond)
{
    extern __shared__ char smem[];
    const uint32_t sb = smem_u32(smem);
    float* bbs = (float*)(smem + PH_BB);
    char* X0g = smem + PH_X0;
    char* X1g = smem + PH_X1;
    char* X2g = smem + PH_X2;

    const int tid = threadIdx.x, lane = tid & 31, wid = tid >> 5;
    const int group = lane >> 2, tq = lane & 3;
    const int wm = wid & 3, wn = wid >> 2;       // 4M x 4N
    const int r0 = wm * 32 + group;

    const int b0 = blockIdx.x * 128;
    const int sg = blockIdx.y;
    const int s0 = 1 + sg * PH_SPG;
    const int sEnd = s0 + PH_SPG;
    if (blockIdx.x == 0 && sg == 0 && tid < 3) cond[tid] = 0.f;

    // ---- stage Wb fp16 resident ----
    for (int u = tid; u < 4096; u += 512) {
        int n = u >> 5, k8 = u & 31;
        cp16(sb + PH_WB + (uint32_t)n * 528 + k8 * 16, &g_Wbh[n * 256 + k8 * 8]);
    }
    CP_COMMIT;
    if (tid < 128) bbs[tid] = bb[tid];

    // ---- stage X_{s0-1} -> X0, X_{s0} -> X1 ----
#pragma unroll
    for (int i = 0; i < 4; i++) {
        int idx = tid + i * 512;
        int row = idx >> 4, c8 = idx & 15;
        const float4* pp = reinterpret_cast<const float4*>(
            src + ((size_t)(s0 - 1) * 2048 + b0 + row) * 128 + c8 * 8);
        const float4* pc = reinterpret_cast<const float4*>(
            src + ((size_t)s0 * 2048 + b0 + row) * 128 + c8 * 8);
        float4 pl = pp[0], ph = pp[1], cl = pc[0], ch = pc[1];
        *reinterpret_cast<uint4*>(X0g + row * 272 + c8 * 16) =
            make_uint4(hpack2(pl.x, pl.y), hpack2(pl.z, pl.w),
                       hpack2(ph.x, ph.y), hpack2(ph.z, ph.w));
        *reinterpret_cast<uint4*>(X1g + row * 272 + c8 * 16) =
            make_uint4(hpack2(cl.x, cl.y), hpack2(cl.z, cl.w),
                       hpack2(ch.x, ch.y), hpack2(ch.z, ch.w));
    }
    CP_WAIT0;
    __syncthreads();

    // LDSM addressing
    const int lm = lane & 15, lh = lane >> 4;
    const int bn = (lane & 7) + ((lane >> 4) << 3);
    const int bkB = ((lane >> 3) & 1) * 16;
    const uint32_t aoff0 = (uint32_t)(wm * 32 + lm) * 272 + lh * 16;
    const uint32_t aoff1 = aoff0 + 16 * 272;
    const uint32_t bW0 = sb + PH_WB + (uint32_t)(wn * 32 + bn) * 528 + bkB;
    const uint32_t bW1 = bW0 + 16 * 528;

    // One step: consume P (X_{s-1}) and C (X_s); refill D with X_{s+1}.
    auto do_step = [&](int s, uint32_t P, uint32_t C, char* Dg) {
        float acc[8][4];
#pragma unroll
        for (int i = 0; i < 8; i++) { acc[i][0] = acc[i][1] = acc[i][2] = acc[i][3] = 0.f; }

        // ksteps 0..7: A = P, B = Wb k 0..127
#pragma unroll
        for (int ks = 0; ks < 8; ks++) {
            unsigned A0[4], A1[4], B0f[4], B1f[4];
            LDSM4(A0,  P + aoff0 + ks * 32);
            LDSM4(A1,  P + aoff1 + ks * 32);
            LDSM4(B0f, bW0 + ks * 32);
            LDSM4(B1f, bW1 + ks * 32);
            mma16h(acc[0], A0, B0f);  mma16h(acc[1], A0, B0f + 2);
            mma16h(acc[2], A0, B1f);  mma16h(acc[3], A0, B1f + 2);
            mma16h(acc[4], A1, B0f);  mma16h(acc[5], A1, B0f + 2);
            mma16h(acc[6], A1, B1f);  mma16h(acc[7], A1, B1f + 2);
        }

        // prefetch X_{s+1} into registers (D is free — no barrier needed)
        const bool pf = (s + 1 < sEnd);
        float4 xr[8];
        if (pf) {
#pragma unroll
            for (int i = 0; i < 4; i++) {
                int idx = tid + i * 512;
                int row = idx >> 4, c8 = idx & 15;
                const float4* p = reinterpret_cast<const float4*>(
                    src + ((size_t)(s + 1) * 2048 + b0 + row) * 128 + c8 * 8);
                xr[i * 2]     = p[0];
                xr[i * 2 + 1] = p[1];
            }
        }

        // ksteps 8..15: A = C, B = Wb k 128..255
#pragma unroll
        for (int ks = 8; ks < 16; ks++) {
            unsigned A0[4], A1[4], B0f[4], B1f[4];
            LDSM4(A0,  C + aoff0 + (ks - 8) * 32);
            LDSM4(A1,  C + aoff1 + (ks - 8) * 32);
            LDSM4(B0f, bW0 + ks * 32);
            LDSM4(B1f, bW1 + ks * 32);
            mma16h(acc[0], A0, B0f);  mma16h(acc[1], A0, B0f + 2);
            mma16h(acc[2], A0, B1f);  mma16h(acc[3], A0, B1f + 2);
            mma16h(acc[4], A1, B0f);  mma16h(acc[5], A1, B0f + 2);
            mma16h(acc[6], A1, B1f);  mma16h(acc[7], A1, B1f + 2);
        }

        // store prefetched X_{s+1} into D
        if (pf) {
#pragma unroll
            for (int i = 0; i < 4; i++) {
                int idx = tid + i * 512;
                int row = idx >> 4, c8 = idx & 15;
                float4 lo = xr[i * 2], hi = xr[i * 2 + 1];
                *reinterpret_cast<uint4*>(Dg + row * 272 + c8 * 16) =
                    make_uint4(hpack2(lo.x, lo.y), hpack2(lo.z, lo.w),
                               hpack2(hi.x, hi.y), hpack2(hi.z, hi.w));
            }
        }

        // epilogue: gelu(acc + bb) -> diffs[s-1]
        {
            float2* og2 = (float2*)(out_diffs + ((size_t)(s - 1) * 2048 + b0) * 128);
#pragma unroll
            for (int mt = 0; mt < 2; mt++) {
#pragma unroll
                for (int nt = 0; nt < 4; nt++) {
                    int col = wn * 32 + nt * 8 + 2 * tq;
                    int rA = r0 + mt * 16, rB = rA + 8;
                    float bi0 = bbs[col], bi1 = bbs[col + 1];
                    float* v = acc[mt * 4 + nt];
                    og2[rA * 64 + (col >> 1)] = make_float2(gelu_exact(v[0] + bi0),
                                                            gelu_exact(v[1] + bi1));
                    og2[rB * 64 + (col >> 1)] = make_float2(gelu_exact(v[2] + bi0),
                                                            gelu_exact(v[3] + bi1));
                }
            }
        }
        __syncthreads();   // D stores visible before next step reads D as C;
                           // also orders this step's P reads before next-next write
    };

    // 15 steps = 5 rotations of (X0,X1,X2) -> (X1,X2,X0) -> (X2,X0,X1)
    int s = s0;
#pragma unroll 1
    for (int it = 0; it < 5; ++it) {
        do_step(s, sb + PH_X0, sb + PH_X1, X2g); ++s;
        do_step(s, sb + PH_X1, sb + PH_X2, X0g); ++s;
        do_step(s, sb + PH_X2, sb + PH_X0, X1g); ++s;
    }
}

// ---------------------------------------------------------------------------
// launcher
// ---------------------------------------------------------------------------
extern "C" void kernel_launch(void* const* d_in, const int* in_sizes, int n_in,
                              void* d_out, int out_size)
{
    const float* src   = (const float*)d_in[0];
    const float* Wb    = (const float*)d_in[1];
    const float* bb    = (const float*)d_in[2];
    const float* W1    = (const float*)d_in[3];
    const float* b1    = (const float*)d_in[4];
    const float* W2    = (const float*)d_in[5];
    const float* b2    = (const float*)d_in[6];
    const float* gamma = (const float*)d_in[7];
    const float* beta  = (const float*)d_in[8];
    float* out = (float*)d_out;

    cudaFuncSetAttribute(fused_main_kernel, cudaFuncAttributeMaxDynamicSharedMemorySize, FB_SZ);
    cudaFuncSetAttribute(bracket_kernel,    cudaFuncAttributeMaxDynamicSharedMemorySize, PH_SZ);

    prep_weights<<<48, 256>>>(Wb, W1, W2);

    dim3 gA(16, 256);
    dim3 gB(16, PH_SGRP);
    fused_main_kernel<<<gA, 512, FB_SZ>>>(src, b1, b2, gamma, beta, out);
    bracket_kernel<<<gB, 512, PH_SZ>>>(src, bb,
                                       out + RET_ELEMS,
                                       out + RET_ELEMS + DIFF_ELEMS);
}